// round 5
// baseline (speedup 1.0000x reference)
#include <cuda_runtime.h>
#include <cuda_bf16.h>

// Problem constants
#define B_    64
#define N_    128
#define LVLS  3
#define NT    32
#define TL    32
#define H_    256
#define OUT_  10
#define BC    4     // batch chunks per trunk
#define MB    16    // batch rows per chunk

// Scratch (device globals — allocation-free)
__device__ float g_v[LVLS * 1024];
__device__ float g_u[LVLS * 1024];
__device__ float g_partial[LVLS * NT * BC * MB * OUT_];   // 61440 floats

__device__ __forceinline__ float sigmoidf_(float x) {
    return 1.0f / (1.0f + __expf(-x));
}

// ---------------------------------------------------------------------------
// Precompute v[l] = W_ih[l] @ w_enc, u[l] = W_ih[l] @ b_enc + b_ih[l] + b_hh[l]
// One thread per (level, gate-row). 3072 rows total.
// ---------------------------------------------------------------------------
__global__ void prep_kernel(const float* __restrict__ W_ih,
                            const float* __restrict__ W_enc,
                            const float* __restrict__ b_enc,
                            const float* __restrict__ b_ih,
                            const float* __restrict__ b_hh) {
    __shared__ float we[H_];
    __shared__ float be[H_];
    int tid = threadIdx.x;                 // 256 threads
    we[tid] = W_enc[tid];
    be[tid] = b_enc[tid];
    __syncthreads();

    int row = blockIdx.x * blockDim.x + tid;   // 0..3071 (global gate row)
    const float4* Wr = reinterpret_cast<const float4*>(W_ih + (size_t)row * H_);
    float sv = 0.f, su = 0.f;
#pragma unroll 8
    for (int k4 = 0; k4 < H_ / 4; k4++) {
        float4 w = __ldg(Wr + k4);
        int k = 4 * k4;
        sv = fmaf(w.x, we[k + 0], sv);
        sv = fmaf(w.y, we[k + 1], sv);
        sv = fmaf(w.z, we[k + 2], sv);
        sv = fmaf(w.w, we[k + 3], sv);
        su = fmaf(w.x, be[k + 0], su);
        su = fmaf(w.y, be[k + 1], su);
        su = fmaf(w.z, be[k + 2], su);
        su = fmaf(w.w, be[k + 3], su);
    }
    g_v[row] = sv;
    g_u[row] = su + b_ih[row] + b_hh[row];
}

// ---------------------------------------------------------------------------
// Main LSTM kernel. One CTA per (level, trunk, batch-chunk): 3*32*4 = 384 CTAs.
// Thread j (0..255) owns gate rows {j, j+256, j+512, j+768} for all MB=16
// batch rows. Runs exactly len(l,t) steps (early exit on trunk length).
// ---------------------------------------------------------------------------
__global__ void __launch_bounds__(256, 2)
lstm_kernel(const float* __restrict__ bf,
            const int*   __restrict__ trunk_idx,
            const int*   __restrict__ trunk_len,
            const float* __restrict__ W_hh,
            const float* __restrict__ W_lin) {
    const int x  = blockIdx.x;          // 0..383
    const int l  = x >> 7;              // 128 CTAs per level
    const int t  = (x >> 2) & 31;
    const int bc = x & 3;
    const int j  = threadIdx.x;         // gate column 0..255

    __shared__ float h_s[MB][H_ + 4];   // pad: row stride 260 floats (16B-aligned)
    __shared__ float sbf[MB][N_];       // this chunk's batch_feature rows
    __shared__ float v_s[1024];
    __shared__ float u_s[1024];
    __shared__ int   idx_s[TL];
    __shared__ int   len_s;

#pragma unroll
    for (int i = 0; i < 4; i++) {
        v_s[j + 256 * i] = g_v[l * 1024 + j + 256 * i];
        u_s[j + 256 * i] = g_u[l * 1024 + j + 256 * i];
    }
    for (int i = j; i < MB * N_; i += 256)
        sbf[i >> 7][i & 127] = bf[(bc * MB + (i >> 7)) * N_ + (i & 127)];
    if (j < TL) idx_s[j] = trunk_idx[(l * NT + t) * TL + j];
    if (j == 0) {
        int L = trunk_len[l * NT + t];
        len_s = min(max(L, 1), TL);
    }
#pragma unroll
    for (int m = 0; m < MB; m++) h_s[m][j] = 0.f;
    __syncthreads();

    const int len = len_s;
    // W_hh row pointers for this thread's 4 gate rows (i,f,g,o at j, j+256, ...)
    const float4* W0 = reinterpret_cast<const float4*>(
        W_hh + (size_t)l * 1024 * H_ + (size_t)j * H_);
    // gate g row offset = g*256 rows * 256 floats = g*65536 floats = g*16384 float4

    float c[MB];
#pragma unroll
    for (int m = 0; m < MB; m++) c[m] = 0.f;

    float vj[4], uj[4];
#pragma unroll
    for (int g = 0; g < 4; g++) {
        vj[g] = v_s[g * 256 + j];
        uj[g] = u_s[g * 256 + j];
    }

    for (int step = 0; step < len; step++) {
        const int n = idx_s[step];
        float a0[MB], a1[MB], a2[MB], a3[MB];
#pragma unroll
        for (int m = 0; m < MB; m++) {
            float s = sbf[m][n];                 // broadcast LDS
            a0[m] = fmaf(s, vj[0], uj[0]);
            a1[m] = fmaf(s, vj[1], uj[1]);
            a2[m] = fmaf(s, vj[2], uj[2]);
            a3[m] = fmaf(s, vj[3], uj[3]);
        }

        // gates[m][row_g] += sum_k h[m][k] * W_hh[row_g][k]
#pragma unroll 2
        for (int k4 = 0; k4 < H_ / 4; k4++) {
            const float4 w0 = __ldg(W0 + k4);
            const float4 w1 = __ldg(W0 + 16384 + k4);
            const float4 w2 = __ldg(W0 + 32768 + k4);
            const float4 w3 = __ldg(W0 + 49152 + k4);
#pragma unroll
            for (int m = 0; m < MB; m++) {
                const float4 hv = *reinterpret_cast<const float4*>(&h_s[m][k4 * 4]);
                a0[m] = fmaf(hv.x, w0.x, a0[m]);
                a0[m] = fmaf(hv.y, w0.y, a0[m]);
                a0[m] = fmaf(hv.z, w0.z, a0[m]);
                a0[m] = fmaf(hv.w, w0.w, a0[m]);
                a1[m] = fmaf(hv.x, w1.x, a1[m]);
                a1[m] = fmaf(hv.y, w1.y, a1[m]);
                a1[m] = fmaf(hv.z, w1.z, a1[m]);
                a1[m] = fmaf(hv.w, w1.w, a1[m]);
                a2[m] = fmaf(hv.x, w2.x, a2[m]);
                a2[m] = fmaf(hv.y, w2.y, a2[m]);
                a2[m] = fmaf(hv.z, w2.z, a2[m]);
                a2[m] = fmaf(hv.w, w2.w, a2[m]);
                a3[m] = fmaf(hv.x, w3.x, a3[m]);
                a3[m] = fmaf(hv.y, w3.y, a3[m]);
                a3[m] = fmaf(hv.z, w3.z, a3[m]);
                a3[m] = fmaf(hv.w, w3.w, a3[m]);
            }
        }

        __syncthreads();   // all h_s reads done before overwrite
#pragma unroll
        for (int m = 0; m < MB; m++) {
            float ig = sigmoidf_(a0[m]);
            float fg = sigmoidf_(a1[m]);
            float gg = tanhf(a2[m]);
            float og = sigmoidf_(a3[m]);
            float cm = fmaf(fg, c[m], ig * gg);
            c[m] = cm;
            h_s[m][j] = og * tanhf(cm);
        }
        __syncthreads();   // h_s complete before next step's reads
    }

    // Epilogue: partial[l][t][bc][m][o] = h_last[m] @ W_lin[l][:,o]
    if (j < MB * OUT_) {
        int m = j / OUT_;
        int o = j % OUT_;
        const float* Wl = W_lin + (size_t)l * H_ * OUT_ + o;
        float s = 0.f;
#pragma unroll 8
        for (int d = 0; d < H_; d++)
            s = fmaf(h_s[m][d], Wl[d * OUT_], s);
        g_partial[(((size_t)(l * NT + t) * BC + bc) * MB + m) * OUT_ + o] = s;
    }
}

// ---------------------------------------------------------------------------
// Deterministic final reduction: out[b][o] = sum_l ( b_lin[l][o]
//                    + sum_t partial[l][t][bc(b)][m(b)][o] )
// ---------------------------------------------------------------------------
__global__ void reduce_kernel(const float* __restrict__ b_lin,
                              float* __restrict__ out) {
    int i = blockIdx.x * blockDim.x + threadIdx.x;
    if (i >= B_ * OUT_) return;
    int b  = i / OUT_;
    int o  = i % OUT_;
    int bc = b / MB;
    int m  = b % MB;
    float s = 0.f;
#pragma unroll
    for (int l = 0; l < LVLS; l++) {
        s += b_lin[l * OUT_ + o];
        for (int t = 0; t < NT; t++)
            s += g_partial[(((size_t)(l * NT + t) * BC + bc) * MB + m) * OUT_ + o];
    }
    out[i] = s;
}

// ---------------------------------------------------------------------------
extern "C" void kernel_launch(void* const* d_in, const int* in_sizes, int n_in,
                              void* d_out, int out_size) {
    const float* batch_feature = (const float*)d_in[0];
    const int*   trunk_idx     = (const int*)  d_in[1];
    const int*   trunk_len     = (const int*)  d_in[2];
    const float* W_enc         = (const float*)d_in[3];
    const float* b_enc         = (const float*)d_in[4];
    const float* W_ih          = (const float*)d_in[5];
    const float* W_hh          = (const float*)d_in[6];
    const float* b_ih          = (const float*)d_in[7];
    const float* b_hh          = (const float*)d_in[8];
    const float* W_lin         = (const float*)d_in[9];
    const float* b_lin         = (const float*)d_in[10];
    float* out = (float*)d_out;

    prep_kernel<<<12, 256>>>(W_ih, W_enc, b_enc, b_ih, b_hh);
    lstm_kernel<<<LVLS * NT * BC, 256>>>(batch_feature, trunk_idx, trunk_len,
                                         W_hh, W_lin);
    reduce_kernel<<<(B_ * OUT_ + 127) / 128, 128>>>(b_lin, out);
}

// round 6
// speedup vs baseline: 1.6915x; 1.6915x over previous
#include <cuda_runtime.h>
#include <cuda_bf16.h>
#include <cstdint>

// Problem constants
#define B_    64
#define N_    128
#define LVLS  3
#define NT    32
#define TL    32
#define H_    256
#define OUT_  10
#define BC    4              // batch chunks
#define MB    16             // batch rows per chunk
#define NP    8              // batch-row pairs per chunk
#define NJOBS (LVLS*NT*BC)   // 384

// Device-global scratch (allocation-free)
__device__ float  g_v[LVLS * 1024];
__device__ float  g_u[LVLS * 1024];
__device__ float4 g_Wt4[LVLS * 64 * 1024];           // [l][k4][row] = W_hh[l][row][4k4..4k4+3]
__device__ float  g_partial[NJOBS * MB * OUT_];
__device__ int    g_ticket;

// ---- packed f32x2 helpers (sm_100+) --------------------------------------
__device__ __forceinline__ unsigned long long pack2(float lo, float hi) {
    unsigned long long r;
    asm("mov.b64 %0, {%1, %2};" : "=l"(r) : "f"(lo), "f"(hi));
    return r;
}
__device__ __forceinline__ void unpack2(unsigned long long v, float& lo, float& hi) {
    asm("mov.b64 {%0, %1}, %2;" : "=f"(lo), "=f"(hi) : "l"(v));
}
__device__ __forceinline__ unsigned long long ffma2(unsigned long long a,
                                                    unsigned long long b,
                                                    unsigned long long c) {
    unsigned long long d;
    asm("fma.rn.f32x2 %0, %1, %2, %3;" : "=l"(d) : "l"(a), "l"(b), "l"(c));
    return d;
}

__device__ __forceinline__ float fast_sig(float x) {
    return __fdividef(1.0f, 1.0f + __expf(-x));
}
__device__ __forceinline__ float fast_tanh(float x) {
    float s = __fdividef(1.0f, 1.0f + __expf(-2.0f * x));
    return fmaf(2.0f, s, -1.0f);
}

// ---------------------------------------------------------------------------
// prep: v = W_ih@w_enc, u = W_ih@b_enc + b_ih + b_hh; transpose W_hh into
// g_Wt4 (coalesced-by-row layout); reset the work ticket.
// grid = 12 blocks x 256 threads: one thread per global gate row r in [0,3072).
// ---------------------------------------------------------------------------
__global__ void prep_kernel(const float* __restrict__ W_ih,
                            const float* __restrict__ W_enc,
                            const float* __restrict__ b_enc,
                            const float* __restrict__ b_ih,
                            const float* __restrict__ b_hh,
                            const float* __restrict__ W_hh) {
    __shared__ float we[H_];
    __shared__ float be[H_];
    int tid = threadIdx.x;
    we[tid] = W_enc[tid];
    be[tid] = b_enc[tid];
    __syncthreads();

    int r   = blockIdx.x * 256 + tid;   // 0..3071
    int l   = r >> 10;
    int row = r & 1023;
    const float4* Wr = reinterpret_cast<const float4*>(W_ih + (size_t)r * H_);
    const float4* Hr = reinterpret_cast<const float4*>(W_hh + (size_t)r * H_);
    float4* dst = g_Wt4 + (((size_t)l) << 16) + row;    // + (k4<<10) per step

    float sv = 0.f, su = 0.f;
#pragma unroll 4
    for (int k4 = 0; k4 < 64; k4++) {
        float4 w = __ldg(Wr + k4);
        int k = 4 * k4;
        sv = fmaf(w.x, we[k + 0], sv); sv = fmaf(w.y, we[k + 1], sv);
        sv = fmaf(w.z, we[k + 2], sv); sv = fmaf(w.w, we[k + 3], sv);
        su = fmaf(w.x, be[k + 0], su); su = fmaf(w.y, be[k + 1], su);
        su = fmaf(w.z, be[k + 2], su); su = fmaf(w.w, be[k + 3], su);
        dst[k4 << 10] = __ldg(Hr + k4);                  // transpose store (coalesced)
    }
    g_v[r] = sv;
    g_u[r] = su + b_ih[r] + b_hh[r];
    if (r == 0) g_ticket = 0;
}

// ---------------------------------------------------------------------------
// Main LSTM: persistent CTAs claim jobs (l,t,bc) via atomic ticket.
// Thread j owns gate rows {j, j+256, j+512, j+768} for 8 batch-row PAIRS,
// accumulated with packed fma.rn.f32x2 (h pre-paired in shared).
// ---------------------------------------------------------------------------
__global__ void __launch_bounds__(256, 1)
lstm_kernel(const float* __restrict__ bf,
            const int*   __restrict__ trunk_idx,
            const int*   __restrict__ trunk_len,
            const float* __restrict__ W_lin) {
    const int j = threadIdx.x;    // gate column 0..255

    __shared__ float2 hp[NP][H_];     // paired hidden state: {h[2p][k], h[2p+1][k]}
    __shared__ float2 sbf2[NP][N_];   // paired batch_feature rows
    __shared__ int    idx_s[TL];
    __shared__ int    job_s;
    __shared__ int    len_s;

    for (;;) {
        if (j == 0) job_s = atomicAdd(&g_ticket, 1);
        __syncthreads();
        const int job = job_s;
        if (job >= NJOBS) break;

        const int l  = job >> 7;
        const int t  = (job >> 2) & 31;
        const int bc = job & 3;

        // ---- per-job loads ----
        float vj[4], uj[4];
#pragma unroll
        for (int g = 0; g < 4; g++) {
            vj[g] = g_v[l * 1024 + (g << 8) + j];
            uj[g] = g_u[l * 1024 + (g << 8) + j];
        }
        for (int i = j; i < NP * N_; i += 256) {
            int p = i >> 7, n = i & 127;
            int row0 = bc * MB + 2 * p;
            sbf2[p][n] = make_float2(bf[row0 * N_ + n], bf[(row0 + 1) * N_ + n]);
        }
        if (j < TL) idx_s[j] = trunk_idx[(l * NT + t) * TL + j];
        if (j == 0) {
            int L = trunk_len[l * NT + t];
            len_s = min(max(L, 1), TL);
        }
#pragma unroll
        for (int p = 0; p < NP; p++) hp[p][j] = make_float2(0.f, 0.f);
        __syncthreads();

        const int len = len_s;
        float c[MB];
#pragma unroll
        for (int m = 0; m < MB; m++) c[m] = 0.f;

        const float4* Wk = g_Wt4 + (((size_t)l) << 16) + j;  // + (k4<<10) + g*256

        for (int step = 0; step < len; step++) {
            const int n = idx_s[step];

            // acc init: gates = s*v + u   (paired over batch rows)
            unsigned long long acc[4][8];
#pragma unroll
            for (int g = 0; g < 4; g++) {
                unsigned long long vv = pack2(vj[g], vj[g]);
                unsigned long long uu = pack2(uj[g], uj[g]);
#pragma unroll
                for (int p = 0; p < NP; p++) {
                    unsigned long long sp =
                        *reinterpret_cast<const unsigned long long*>(&sbf2[p][n]);
                    acc[g][p] = ffma2(sp, vv, uu);
                }
            }

            // recurrent GEMM: acc[g][p] += sum_k h2[p][k] * W[g*256+j][k]
#pragma unroll 2
            for (int k4 = 0; k4 < 64; k4++) {
                const float4 w0 = __ldg(Wk + (k4 << 10));
                const float4 w1 = __ldg(Wk + (k4 << 10) + 256);
                const float4 w2 = __ldg(Wk + (k4 << 10) + 512);
                const float4 w3 = __ldg(Wk + (k4 << 10) + 768);
                unsigned long long wp[4][4];
                wp[0][0] = pack2(w0.x, w0.x); wp[0][1] = pack2(w0.y, w0.y);
                wp[0][2] = pack2(w0.z, w0.z); wp[0][3] = pack2(w0.w, w0.w);
                wp[1][0] = pack2(w1.x, w1.x); wp[1][1] = pack2(w1.y, w1.y);
                wp[1][2] = pack2(w1.z, w1.z); wp[1][3] = pack2(w1.w, w1.w);
                wp[2][0] = pack2(w2.x, w2.x); wp[2][1] = pack2(w2.y, w2.y);
                wp[2][2] = pack2(w2.z, w2.z); wp[2][3] = pack2(w2.w, w2.w);
                wp[3][0] = pack2(w3.x, w3.x); wp[3][1] = pack2(w3.y, w3.y);
                wp[3][2] = pack2(w3.z, w3.z); wp[3][3] = pack2(w3.w, w3.w);
#pragma unroll
                for (int p = 0; p < NP; p++) {
                    const ulonglong2 qa =
                        *reinterpret_cast<const ulonglong2*>(&hp[p][k4 * 4]);
                    const ulonglong2 qb =
                        *reinterpret_cast<const ulonglong2*>(&hp[p][k4 * 4 + 2]);
#pragma unroll
                    for (int g = 0; g < 4; g++) {
                        acc[g][p] = ffma2(qa.x, wp[g][0], acc[g][p]);
                        acc[g][p] = ffma2(qa.y, wp[g][1], acc[g][p]);
                        acc[g][p] = ffma2(qb.x, wp[g][2], acc[g][p]);
                        acc[g][p] = ffma2(qb.y, wp[g][3], acc[g][p]);
                    }
                }
            }

            __syncthreads();   // all hp reads done before overwrite
#pragma unroll
            for (int p = 0; p < NP; p++) {
                float i0, i1, f0, f1, g0, g1, o0, o1;
                unpack2(acc[0][p], i0, i1);
                unpack2(acc[1][p], f0, f1);
                unpack2(acc[2][p], g0, g1);
                unpack2(acc[3][p], o0, o1);
                int m0 = 2 * p, m1 = 2 * p + 1;
                float c0 = fmaf(fast_sig(f0), c[m0], fast_sig(i0) * fast_tanh(g0));
                float c1 = fmaf(fast_sig(f1), c[m1], fast_sig(i1) * fast_tanh(g1));
                c[m0] = c0; c[m1] = c1;
                float h0 = fast_sig(o0) * fast_tanh(c0);
                float h1 = fast_sig(o1) * fast_tanh(c1);
                hp[p][j] = make_float2(h0, h1);
            }
            __syncthreads();   // hp complete before next step
        }

        // ---- epilogue: partial[m][o] = h_last[m] @ W_lin[l][:,o] ----
        if (j < MB * OUT_) {
            int m = j / OUT_;
            int o = j - m * OUT_;
            int p = m >> 1;
            int hi = m & 1;
            const float* Wl = W_lin + (size_t)l * H_ * OUT_ + o;
            float s = 0.f;
#pragma unroll 8
            for (int d = 0; d < H_; d++) {
                float hv = hi ? hp[p][d].y : hp[p][d].x;
                s = fmaf(hv, __ldg(Wl + d * OUT_), s);
            }
            g_partial[(job * MB + m) * OUT_ + o] = s;
        }
        __syncthreads();   // protect hp/sbf2/job_s before next job
    }
}

// ---------------------------------------------------------------------------
// Deterministic final reduction over trunks and levels (+ b_lin per level).
// ---------------------------------------------------------------------------
__global__ void reduce_kernel(const float* __restrict__ b_lin,
                              float* __restrict__ out) {
    int i = blockIdx.x * blockDim.x + threadIdx.x;
    if (i >= B_ * OUT_) return;
    int b  = i / OUT_;
    int o  = i % OUT_;
    int bc = b / MB;
    int m  = b % MB;
    float s = 0.f;
#pragma unroll
    for (int l = 0; l < LVLS; l++) {
        s += b_lin[l * OUT_ + o];
        for (int t = 0; t < NT; t++) {
            int job = (l * NT + t) * BC + bc;
            s += g_partial[(job * MB + m) * OUT_ + o];
        }
    }
    out[i] = s;
}

// ---------------------------------------------------------------------------
extern "C" void kernel_launch(void* const* d_in, const int* in_sizes, int n_in,
                              void* d_out, int out_size) {
    const float* batch_feature = (const float*)d_in[0];
    const int*   trunk_idx     = (const int*)  d_in[1];
    const int*   trunk_len     = (const int*)  d_in[2];
    const float* W_enc         = (const float*)d_in[3];
    const float* b_enc         = (const float*)d_in[4];
    const float* W_ih          = (const float*)d_in[5];
    const float* W_hh          = (const float*)d_in[6];
    const float* b_ih          = (const float*)d_in[7];
    const float* b_hh          = (const float*)d_in[8];
    const float* W_lin         = (const float*)d_in[9];
    const float* b_lin         = (const float*)d_in[10];
    float* out = (float*)d_out;

    prep_kernel<<<12, 256>>>(W_ih, W_enc, b_enc, b_ih, b_hh, W_hh);
    lstm_kernel<<<NJOBS, 256>>>(batch_feature, trunk_idx, trunk_len, W_lin);
    reduce_kernel<<<(B_ * OUT_ + 127) / 128, 128>>>(b_lin, out);
}

// round 7
// speedup vs baseline: 2.2217x; 1.3134x over previous
#include <cuda_runtime.h>
#include <cuda_bf16.h>
#include <cstdint>

// Problem constants
#define B_    64
#define N_    128
#define LVLS  3
#define NT    32
#define TL    32
#define H_    256
#define OUT_  10
#define BC    4              // batch chunks
#define MB    16             // batch rows per chunk
#define NP    8              // batch-row pairs per chunk
#define NJOBS (LVLS*NT*BC)   // 384

// Device-global scratch (allocation-free)
__device__ float  g_v[LVLS * 1024];
__device__ float  g_u[LVLS * 1024];
__device__ float4 g_Wt4[LVLS * 64 * 1024];   // [l][k4][row] = W_hh[l][row][4k4..+3]
__device__ float  g_partial[NJOBS * MB * OUT_];
__device__ int    g_order[NJOBS];
__device__ int    g_ticket;

// ---- packed f32x2 helpers (sm_100+) --------------------------------------
__device__ __forceinline__ unsigned long long pack2(float lo, float hi) {
    unsigned long long r;
    asm("mov.b64 %0, {%1, %2};" : "=l"(r) : "f"(lo), "f"(hi));
    return r;
}
__device__ __forceinline__ void unpack2(unsigned long long v, float& lo, float& hi) {
    asm("mov.b64 {%0, %1}, %2;" : "=f"(lo), "=f"(hi) : "l"(v));
}
__device__ __forceinline__ unsigned long long ffma2(unsigned long long a,
                                                    unsigned long long b,
                                                    unsigned long long c) {
    unsigned long long d;
    asm("fma.rn.f32x2 %0, %1, %2, %3;" : "=l"(d) : "l"(a), "l"(b), "l"(c));
    return d;
}

__device__ __forceinline__ float fast_sig(float x) {
    return __fdividef(1.0f, 1.0f + __expf(-x));
}
__device__ __forceinline__ float fast_tanh(float x) {
    float s = __fdividef(1.0f, 1.0f + __expf(-2.0f * x));
    return fmaf(2.0f, s, -1.0f);
}

// ---------------------------------------------------------------------------
// prep: v = W_ih@w_enc, u = W_ih@b_enc + b_ih + b_hh; transpose W_hh into
// g_Wt4 (coalesced-by-row layout). One thread per global gate row (3072).
// ---------------------------------------------------------------------------
__global__ void prep_kernel(const float* __restrict__ W_ih,
                            const float* __restrict__ W_enc,
                            const float* __restrict__ b_enc,
                            const float* __restrict__ b_ih,
                            const float* __restrict__ b_hh,
                            const float* __restrict__ W_hh) {
    __shared__ float we[H_];
    __shared__ float be[H_];
    int tid = threadIdx.x;
    we[tid] = W_enc[tid];
    be[tid] = b_enc[tid];
    __syncthreads();

    int r   = blockIdx.x * 256 + tid;   // 0..3071
    int l   = r >> 10;
    int row = r & 1023;
    const float4* Wr = reinterpret_cast<const float4*>(W_ih + (size_t)r * H_);
    const float4* Hr = reinterpret_cast<const float4*>(W_hh + (size_t)r * H_);
    float4* dst = g_Wt4 + (((size_t)l) << 16) + row;

    float sv = 0.f, su = 0.f;
#pragma unroll 4
    for (int k4 = 0; k4 < 64; k4++) {
        float4 w = __ldg(Wr + k4);
        int k = 4 * k4;
        sv = fmaf(w.x, we[k + 0], sv); sv = fmaf(w.y, we[k + 1], sv);
        sv = fmaf(w.z, we[k + 2], sv); sv = fmaf(w.w, we[k + 3], sv);
        su = fmaf(w.x, be[k + 0], su); su = fmaf(w.y, be[k + 1], su);
        su = fmaf(w.z, be[k + 2], su); su = fmaf(w.w, be[k + 3], su);
        dst[k4 << 10] = __ldg(Hr + k4);
    }
    g_v[r] = sv;
    g_u[r] = su + b_ih[r] + b_hh[r];
}

// ---------------------------------------------------------------------------
// order: rank jobs by descending trunk length (LPT scheduling) + ticket reset.
// ---------------------------------------------------------------------------
__global__ void order_kernel(const int* __restrict__ trunk_len) {
    __shared__ int len_s[NJOBS];
    int i = threadIdx.x;               // 0..383
    int l = i >> 7;
    int t = (i >> 2) & 31;
    int L = trunk_len[l * NT + t];
    L = min(max(L, 1), TL);
    len_s[i] = L;
    __syncthreads();
    int Li = len_s[i];
    int rank = 0;
    for (int k = 0; k < NJOBS; k++) {
        int Lk = len_s[k];
        rank += (Lk > Li) || (Lk == Li && k < i);
    }
    g_order[rank] = i;
    if (i == 0) g_ticket = 0;
}

// ---------------------------------------------------------------------------
// Main LSTM: 512-thread persistent CTAs, longest-job-first ticket dispatch.
// Thread (j = tid&255, h = tid>>8) owns all 4 gate rows {j,j+256,j+512,j+768}
// for row-pairs [4h, 4h+4). FFMA2 (f32x2) accumulation, gates processed two
// at a time to bound live registers.
// ---------------------------------------------------------------------------
__global__ void __launch_bounds__(512, 1)
lstm_kernel(const float* __restrict__ bf,
            const int*   __restrict__ trunk_idx,
            const int*   __restrict__ trunk_len,
            const float* __restrict__ W_lin) {
    const int tid = threadIdx.x;
    const int j   = tid & 255;
    const int h   = tid >> 8;          // pair-half: pairs [4h, 4h+4)

    __shared__ float2 hp[NP][H_];      // paired hidden state
    __shared__ float2 sbf2[NP][N_];    // paired batch_feature rows
    __shared__ int    idx_s[TL];
    __shared__ int    job_s;
    __shared__ int    len_s;

    for (;;) {
        if (tid == 0) {
            int tk = atomicAdd(&g_ticket, 1);
            job_s = (tk < NJOBS) ? g_order[tk] : -1;
        }
        __syncthreads();
        const int job = job_s;
        if (job < 0) break;

        const int l  = job >> 7;
        const int t  = (job >> 2) & 31;
        const int bc = job & 3;

        float vj[4], uj[4];
#pragma unroll
        for (int g = 0; g < 4; g++) {
            vj[g] = g_v[l * 1024 + (g << 8) + j];
            uj[g] = g_u[l * 1024 + (g << 8) + j];
        }
        for (int i = tid; i < NP * N_; i += 512) {
            int p = i >> 7, n = i & 127;
            int row0 = bc * MB + 2 * p;
            sbf2[p][n] = make_float2(bf[row0 * N_ + n], bf[(row0 + 1) * N_ + n]);
        }
        if (tid < TL) idx_s[tid] = trunk_idx[(l * NT + t) * TL + tid];
        if (tid == 0) {
            int L = trunk_len[l * NT + t];
            len_s = min(max(L, 1), TL);
        }
        for (int i = tid; i < NP * H_; i += 512)
            hp[i >> 8][i & 255] = make_float2(0.f, 0.f);
        __syncthreads();

        const int len = len_s;
        float c[8];
#pragma unroll
        for (int m = 0; m < 8; m++) c[m] = 0.f;

        const float4* Wk = g_Wt4 + (((size_t)l) << 16) + j;  // + (k4<<10) + g*256

        for (int step = 0; step < len; step++) {
            const int n = idx_s[step];

            unsigned long long acc[4][4];   // [gate][pair-in-half]
#pragma unroll
            for (int pp = 0; pp < 4; pp++) {
                float2 s2 = sbf2[4 * h + pp][n];
#pragma unroll
                for (int g = 0; g < 4; g++)
                    acc[g][pp] = pack2(fmaf(s2.x, vj[g], uj[g]),
                                       fmaf(s2.y, vj[g], uj[g]));
            }

            // Recurrent GEMM with periodic re-convergence (keeps the two
            // halves' identical W reads inside the L1 window).
            for (int k8 = 0; k8 < 8; k8++) {
#pragma unroll 2
                for (int kk = 0; kk < 8; kk++) {
                    const int k4 = k8 * 8 + kk;
                    const float4* Wb = Wk + (k4 << 10);
#pragma unroll
                    for (int gh = 0; gh < 2; gh++) {
                        const float4 wa = __ldg(Wb + (2 * gh) * 256);
                        const float4 wb = __ldg(Wb + (2 * gh + 1) * 256);
                        unsigned long long wpa0 = pack2(wa.x, wa.x);
                        unsigned long long wpa1 = pack2(wa.y, wa.y);
                        unsigned long long wpa2 = pack2(wa.z, wa.z);
                        unsigned long long wpa3 = pack2(wa.w, wa.w);
                        unsigned long long wpb0 = pack2(wb.x, wb.x);
                        unsigned long long wpb1 = pack2(wb.y, wb.y);
                        unsigned long long wpb2 = pack2(wb.z, wb.z);
                        unsigned long long wpb3 = pack2(wb.w, wb.w);
#pragma unroll
                        for (int pp = 0; pp < 4; pp++) {
                            const int p = 4 * h + pp;
                            const ulonglong2 qa =
                                *reinterpret_cast<const ulonglong2*>(&hp[p][k4 * 4]);
                            const ulonglong2 qb =
                                *reinterpret_cast<const ulonglong2*>(&hp[p][k4 * 4 + 2]);
                            unsigned long long A = acc[2 * gh][pp];
                            unsigned long long Bq = acc[2 * gh + 1][pp];
                            A  = ffma2(qa.x, wpa0, A);
                            A  = ffma2(qa.y, wpa1, A);
                            A  = ffma2(qb.x, wpa2, A);
                            A  = ffma2(qb.y, wpa3, A);
                            Bq = ffma2(qa.x, wpb0, Bq);
                            Bq = ffma2(qa.y, wpb1, Bq);
                            Bq = ffma2(qb.x, wpb2, Bq);
                            Bq = ffma2(qb.y, wpb3, Bq);
                            acc[2 * gh][pp]     = A;
                            acc[2 * gh + 1][pp] = Bq;
                        }
                    }
                }
                __syncthreads();   // final one doubles as pre-overwrite barrier
            }

#pragma unroll
            for (int pp = 0; pp < 4; pp++) {
                const int p = 4 * h + pp;
                float i0, i1, f0, f1, g0, g1, o0, o1;
                unpack2(acc[0][pp], i0, i1);
                unpack2(acc[1][pp], f0, f1);
                unpack2(acc[2][pp], g0, g1);
                unpack2(acc[3][pp], o0, o1);
                float c0 = fmaf(fast_sig(f0), c[2 * pp],     fast_sig(i0) * fast_tanh(g0));
                float c1 = fmaf(fast_sig(f1), c[2 * pp + 1], fast_sig(i1) * fast_tanh(g1));
                c[2 * pp] = c0; c[2 * pp + 1] = c1;
                hp[p][j] = make_float2(fast_sig(o0) * fast_tanh(c0),
                                       fast_sig(o1) * fast_tanh(c1));
            }
            __syncthreads();
        }

        // ---- epilogue: partial[m][o] = h_last[m] @ W_lin[l][:,o] ----
        if (h == 0 && j < MB * OUT_) {
            int m = j / OUT_;
            int o = j - m * OUT_;
            int p = m >> 1;
            int hi = m & 1;
            const float* Wl = W_lin + (size_t)l * H_ * OUT_ + o;
            float s = 0.f;
#pragma unroll 8
            for (int d = 0; d < H_; d++) {
                float hv = hi ? hp[p][d].y : hp[p][d].x;
                s = fmaf(hv, __ldg(Wl + d * OUT_), s);
            }
            g_partial[(job * MB + m) * OUT_ + o] = s;
        }
        __syncthreads();   // protect shared state before next job
    }
}

// ---------------------------------------------------------------------------
// Deterministic final reduction over trunks and levels (+ b_lin per level).
// ---------------------------------------------------------------------------
__global__ void reduce_kernel(const float* __restrict__ b_lin,
                              float* __restrict__ out) {
    int i = blockIdx.x * blockDim.x + threadIdx.x;
    if (i >= B_ * OUT_) return;
    int b  = i / OUT_;
    int o  = i % OUT_;
    int bc = b / MB;
    int m  = b % MB;
    float s = 0.f;
#pragma unroll
    for (int l = 0; l < LVLS; l++) {
        s += b_lin[l * OUT_ + o];
        for (int t = 0; t < NT; t++) {
            int job = (l * NT + t) * BC + bc;
            s += g_partial[(job * MB + m) * OUT_ + o];
        }
    }
    out[i] = s;
}

// ---------------------------------------------------------------------------
extern "C" void kernel_launch(void* const* d_in, const int* in_sizes, int n_in,
                              void* d_out, int out_size) {
    const float* batch_feature = (const float*)d_in[0];
    const int*   trunk_idx     = (const int*)  d_in[1];
    const int*   trunk_len     = (const int*)  d_in[2];
    const float* W_enc         = (const float*)d_in[3];
    const float* b_enc         = (const float*)d_in[4];
    const float* W_ih          = (const float*)d_in[5];
    const float* W_hh          = (const float*)d_in[6];
    const float* b_ih          = (const float*)d_in[7];
    const float* b_hh          = (const float*)d_in[8];
    const float* W_lin         = (const float*)d_in[9];
    const float* b_lin         = (const float*)d_in[10];
    float* out = (float*)d_out;

    prep_kernel<<<12, 256>>>(W_ih, W_enc, b_enc, b_ih, b_hh, W_hh);
    order_kernel<<<1, NJOBS>>>(trunk_len);
    lstm_kernel<<<NJOBS, 512>>>(batch_feature, trunk_idx, trunk_len, W_lin);
    reduce_kernel<<<(B_ * OUT_ + 127) / 128, 128>>>(b_lin, out);
}